// round 16
// baseline (speedup 1.0000x reference)
#include <cuda_runtime.h>
#include <math.h>

#define BB 4
#define CC 3
#define HH 384
#define WW 384
#define HWSZ (HH * WW)
#define CHW (CC * HWSZ)

#define INV2SC 50.0f            // 1/(2*0.1^2)
#define INV2SS (1.0f / 98.0f)   // 1/(2*7^2)
#define EPS_LP 1e-6f
#define LOG2E 1.4426950408889634f

// Border pixels per image: 2 strips of 3x384 + 378 rows x 6 cols
#define NBORDER (2 * 3 * WW + (HH - 6) * 6)   // 4572
#define NBTOT (NBORDER * BB)                  // 18288
#define NBLK_XY (12 * 48)                     // 576 blocks per z-slice

__device__ __forceinline__ float exp2_f(float x) {
    float r;
    asm("ex2.approx.f32 %0, %1;" : "=f"(r) : "f"(x));
    return r;
}

// lp(d) = (d*d + eps)^0.4
__device__ __forceinline__ float lp_term(float d) {
    return __powf(fmaf(d, d, EPS_LP), 0.4f);
}

// warp -> block reduction, one atomic per block (pre-scaled by 1/n).
// tid MUST be the linear 0..255 thread id within the block.
__device__ __forceinline__ void reduce_add(float acc, float* out, int tid) {
    const unsigned FULL = 0xFFFFFFFFu;
#pragma unroll
    for (int off = 16; off > 0; off >>= 1)
        acc += __shfl_down_sync(FULL, acc, off);
    __shared__ float wsum[8];
    const int wid = tid >> 5, lid = tid & 31;
    if (lid == 0) wsum[wid] = acc;
    __syncthreads();
    if (wid == 0) {
        float v = (lid < 8) ? wsum[lid] : 0.0f;
#pragma unroll
        for (int off = 4; off > 0; off >>= 1)
            v += __shfl_down_sync(FULL, v, off);
        if (lid == 0) {
            const float inv_n = 1.0f / (float)(BB * CC * HH * WW);
            atomicAdd(out, v * inv_n);
        }
    }
}

// Border path: clamped (out-of-bounds) ordered terms, weight 1. z == 0 slice.
// STRIPED mapping (idx = tid*576 + bid): every slice-0 block carries only
// ~32 border pixels (1 active warp), so border latency hides under the hot
// blocks co-resident on the same SM (the old 72-block clustering left ~2us
// of border work on the critical path).
__device__ __noinline__ void border_path(const float* __restrict__ inp,
                                         const float* __restrict__ tgt,
                                         float* __restrict__ out, int tid) {
    const int bid = blockIdx.y * gridDim.x + blockIdx.x;
    const int idx = tid * NBLK_XY + bid;    // striped across all 576 blocks
    float acc = 0.0f;

    if (idx < NBTOT) {
        const int b = idx / NBORDER;
        const int r = idx % NBORDER;
        int x, y;
        if (r < 3 * WW) {                    // top rows 0..2
            y = r / WW; x = r % WW;
        } else if (r < 6 * WW) {             // bottom rows 381..383
            const int r2 = r - 3 * WW;
            y = (HH - 3) + r2 / WW; x = r2 % WW;
        } else {                             // side cols, rows 3..380
            const int r3 = r - 6 * WW;
            y = 3 + r3 / 6;
            const int c = r3 % 6;
            x = (c < 3) ? c : (WW - 6 + c);
        }
        const int pidx = y * WW + x;
        const float* pi = inp + b * CHW + pidx;
        const float* pt = tgt + b * CHW + pidx;

        const float i0 = pi[0], i1 = pi[HWSZ], i2 = pi[2 * HWSZ];
        const float t0 = pt[0], t1 = pt[HWSZ], t2 = pt[2 * HWSZ];

        float wky[4];
        wky[0] = 1.0f;
        wky[1] = __expf(-1.0f * INV2SS);
        wky[2] = __expf(-4.0f * INV2SS);
        wky[3] = __expf(-9.0f * INV2SS);

#pragma unroll 1
        for (int dy = -3; dy <= 3; dy++) {
#pragma unroll 1
            for (int dx = -3; dx <= 3; dx++) {
                if (dy == 0 && dx == 0) continue;
                int qx = x + dx, qy = y + dy;
                const bool oob = ((unsigned)qx >= (unsigned)WW) ||
                                 ((unsigned)qy >= (unsigned)HH);
                if (oob) {
                    qx = qx < 0 ? 0 : (qx >= WW ? WW - 1 : qx);
                    qy = qy < 0 ? 0 : (qy >= HH ? HH - 1 : qy);
                    const int q = (qy - y) * WW + (qx - x);

                    const float iq0 = __ldg(pi + q);
                    const float iq1 = __ldg(pi + q + HWSZ);
                    const float iq2 = __ldg(pi + q + 2 * HWSZ);
                    const float tq0 = __ldg(pt + q);
                    const float tq1 = __ldg(pt + q + HWSZ);
                    const float tq2 = __ldg(pt + q + 2 * HWSZ);

                    const float d0 = i0 - iq0, d1 = i1 - iq1, d2 = i2 - iq2;
                    const float e0 = t0 - tq0, e1 = t1 - tq1, e2 = t2 - tq2;

                    const float cd = fmaf(e0, e0, fmaf(e1, e1, e2 * e2));
                    const int ady = dy < 0 ? -dy : dy;
                    const int adx = dx < 0 ? -dx : dx;
                    const float ws = wky[ady] * wky[adx];
                    const float sconst = (float)(dy * dy + dx * dx) * INV2SS;
                    const float wcs = __expf(-fmaf(cd, INV2SC, sconst));

                    const float sm = lp_term(d0) + lp_term(d1) + lp_term(d2);
                    const float ed = lp_term(fabsf(d0) - fabsf(e0))
                                   + lp_term(fabsf(d1) - fabsf(e1))
                                   + lp_term(fabsf(d2) - fabsf(e2));

                    acc = fmaf(wcs, sm, acc);
                    acc = fmaf(ws - wcs, ed, acc);
                }
            }
        }
    }

    reduce_add(acc, out, tid);
}

// z == 0: border slice (striped over all 576 blocks, overlaps hot waves).
// z >= 1: clean hot path for image b = z-1 — the converged optimum body.
__global__ __launch_bounds__(256)
void loss_kernel(const float* __restrict__ inp,
                 const float* __restrict__ tgt,
                 float* __restrict__ out) {
    const int tid = threadIdx.y * 32 + threadIdx.x;
    if (blockIdx.z == 0) {
        border_path(inp, tgt, out, tid);
        return;
    }
    const int b = blockIdx.z - 1;

    const int x = blockIdx.x * 32 + threadIdx.x;
    const int y = blockIdx.y * 8 + threadIdx.y;
    const int pidx = y * WW + x;

    const float* pi = inp + b * CHW + pidx;
    const float* pt = tgt + b * CHW + pidx;

    const float i0 = pi[0], i1 = pi[HWSZ], i2 = pi[2 * HWSZ];
    const float t0 = pt[0], t1 = pt[HWSZ], t2 = pt[2 * HWSZ];

    float wky[4];
    wky[0] = 1.0f;
    wky[1] = __expf(-1.0f * INV2SS);
    wky[2] = __expf(-4.0f * INV2SS);
    wky[3] = __expf(-9.0f * INV2SS);

    float pacc = 0.0f;

#pragma unroll
    for (int dy = 0; dy <= 3; dy++) {
        const bool vy = (y + dy) < HH;
#pragma unroll
        for (int dx = -3; dx <= 3; dx++) {
            if (dy == 0 && dx <= 0) continue;      // compile-time
            const bool v = vy && ((unsigned)(x + dx) < (unsigned)WW);
            if (v) {
                const int q = dy * WW + dx;        // compile-time immediate
                const float iq0 = __ldg(pi + q);
                const float iq1 = __ldg(pi + q + HWSZ);
                const float iq2 = __ldg(pi + q + 2 * HWSZ);
                const float tq0 = __ldg(pt + q);
                const float tq1 = __ldg(pt + q + HWSZ);
                const float tq2 = __ldg(pt + q + 2 * HWSZ);

                const float d0 = i0 - iq0, d1 = i1 - iq1, d2 = i2 - iq2;
                const float e0 = t0 - tq0, e1 = t1 - tq1, e2 = t2 - tq2;

                const float cd = fmaf(e0, e0, fmaf(e1, e1, e2 * e2));
                const int adx = dx < 0 ? -dx : dx;
                const float ws = wky[dy] * wky[adx];
                // wcs = ws*wc = exp2(-(cd*50 + s/98)*log2e): FFMA + EX2 only
                const float sc2 = -(float)(dy * dy + dx * dx) * INV2SS * LOG2E;
                const float wcs = exp2_f(fmaf(cd, -INV2SC * LOG2E, sc2));

                const float sm = lp_term(d0) + lp_term(d1) + lp_term(d2);
                const float ed = lp_term(fabsf(d0) - fabsf(e0))
                               + lp_term(fabsf(d1) - fabsf(e1))
                               + lp_term(fabsf(d2) - fabsf(e2));

                pacc = fmaf(wcs, sm, pacc);
                pacc = fmaf(ws - wcs, ed, pacc);
            }
        }
    }

    const float l2 = (i0 - t0) * (i0 - t0)
                   + (i1 - t1) * (i1 - t1)
                   + (i2 - t2) * (i2 - t2);
    const float acc = fmaf(2.0f, pacc, l2);

    reduce_add(acc, out, tid);
}

extern "C" void kernel_launch(void* const* d_in, const int* in_sizes, int n_in,
                              void* d_out, int out_size) {
    (void)in_sizes; (void)n_in;
    const float* inp = (const float*)d_in[0];
    const float* tgt = (const float*)d_in[1];
    float* out = (float*)d_out;

    if (out_size >= 1) cudaMemsetAsync(out, 0, sizeof(float));

    dim3 block(32, 8, 1);
    dim3 grid(WW / 32, HH / 8, BB + 1);   // z==0: border; z-1 = image index
    loss_kernel<<<grid, block>>>(inp, tgt, out);
}

// round 17
// speedup vs baseline: 1.0127x; 1.0127x over previous
#include <cuda_runtime.h>
#include <math.h>

#define BB 4
#define CC 3
#define HH 384
#define WW 384
#define HWSZ (HH * WW)
#define CHW (CC * HWSZ)

#define INV2SC 50.0f            // 1/(2*0.1^2)
#define INV2SS (1.0f / 98.0f)   // 1/(2*7^2)
#define EPS_LP 1e-6f

// Border pixels per image: 2 strips of 3x384 + 378 rows x 6 cols
#define NBORDER (2 * 3 * WW + (HH - 6) * 6)   // 4572
#define NBTOT (NBORDER * BB)                  // 18288
#define NBBLK ((NBTOT + 255) / 256)           // 72

// lp(d) = (d*d + eps)^0.4
__device__ __forceinline__ float lp_term(float d) {
    return __powf(fmaf(d, d, EPS_LP), 0.4f);
}

// warp -> block reduction, one atomic per block (pre-scaled by 1/n).
// tid MUST be the linear 0..255 thread id within the block.
__device__ __forceinline__ void reduce_add(float acc, float* out, int tid) {
    const unsigned FULL = 0xFFFFFFFFu;
#pragma unroll
    for (int off = 16; off > 0; off >>= 1)
        acc += __shfl_down_sync(FULL, acc, off);
    __shared__ float wsum[8];
    const int wid = tid >> 5, lid = tid & 31;
    if (lid == 0) wsum[wid] = acc;
    __syncthreads();
    if (wid == 0) {
        float v = (lid < 8) ? wsum[lid] : 0.0f;
#pragma unroll
        for (int off = 4; off > 0; off >>= 1)
            v += __shfl_down_sync(FULL, v, off);
        if (lid == 0) {
            const float inv_n = 1.0f / (float)(BB * CC * HH * WW);
            atomicAdd(out, v * inv_n);
        }
    }
}

// Border path: only the clamped (out-of-bounds) ordered terms, weight 1.
// Runs in the z == 0 grid slice so these 72 blocks are scheduled FIRST and
// overlap with the first hot wave (at z == BB they ran in the tail: +10us).
__device__ __noinline__ void border_path(const float* __restrict__ inp,
                                         const float* __restrict__ tgt,
                                         float* __restrict__ out, int tid) {
    const int bid = blockIdx.y * gridDim.x + blockIdx.x;
    const int gid = bid * 256 + tid;
    float acc = 0.0f;

    if (gid < NBTOT) {
        const int b = gid / NBORDER;
        const int r = gid % NBORDER;
        int x, y;
        if (r < 3 * WW) {                    // top rows 0..2
            y = r / WW; x = r % WW;
        } else if (r < 6 * WW) {             // bottom rows 381..383
            const int r2 = r - 3 * WW;
            y = (HH - 3) + r2 / WW; x = r2 % WW;
        } else {                             // side cols, rows 3..380
            const int r3 = r - 6 * WW;
            y = 3 + r3 / 6;
            const int c = r3 % 6;
            x = (c < 3) ? c : (WW - 6 + c);  // 0,1,2 or 381,382,383
        }
        const int pidx = y * WW + x;
        const float* pi = inp + b * CHW + pidx;
        const float* pt = tgt + b * CHW + pidx;

        const float i0 = pi[0], i1 = pi[HWSZ], i2 = pi[2 * HWSZ];
        const float t0 = pt[0], t1 = pt[HWSZ], t2 = pt[2 * HWSZ];

        float wky[4];
        wky[0] = 1.0f;
        wky[1] = __expf(-1.0f * INV2SS);
        wky[2] = __expf(-4.0f * INV2SS);
        wky[3] = __expf(-9.0f * INV2SS);

#pragma unroll 1
        for (int dy = -3; dy <= 3; dy++) {
#pragma unroll 1
            for (int dx = -3; dx <= 3; dx++) {
                if (dy == 0 && dx == 0) continue;
                int qx = x + dx, qy = y + dy;
                const bool oob = ((unsigned)qx >= (unsigned)WW) ||
                                 ((unsigned)qy >= (unsigned)HH);
                if (oob) {
                    qx = qx < 0 ? 0 : (qx >= WW ? WW - 1 : qx);
                    qy = qy < 0 ? 0 : (qy >= HH ? HH - 1 : qy);
                    const int q = (qy - y) * WW + (qx - x);  // rel to pidx

                    const float iq0 = __ldg(pi + q);
                    const float iq1 = __ldg(pi + q + HWSZ);
                    const float iq2 = __ldg(pi + q + 2 * HWSZ);
                    const float tq0 = __ldg(pt + q);
                    const float tq1 = __ldg(pt + q + HWSZ);
                    const float tq2 = __ldg(pt + q + 2 * HWSZ);

                    const float d0 = i0 - iq0, d1 = i1 - iq1, d2 = i2 - iq2;
                    const float e0 = t0 - tq0, e1 = t1 - tq1, e2 = t2 - tq2;

                    const float cd = fmaf(e0, e0, fmaf(e1, e1, e2 * e2));
                    const int ady = dy < 0 ? -dy : dy;
                    const int adx = dx < 0 ? -dx : dx;
                    const float ws = wky[ady] * wky[adx];
                    const float sconst = (float)(dy * dy + dx * dx) * INV2SS;
                    const float wcs = __expf(-fmaf(cd, INV2SC, sconst));

                    const float sm = lp_term(d0) + lp_term(d1) + lp_term(d2);
                    const float ed = lp_term(fabsf(d0) - fabsf(e0))
                                   + lp_term(fabsf(d1) - fabsf(e1))
                                   + lp_term(fabsf(d2) - fabsf(e2));

                    acc = fmaf(wcs, sm, acc);
                    acc = fmaf(ws - wcs, ed, acc);
                }
            }
        }
    }

    reduce_add(acc, out, tid);
}

// z == 0: border slice (72 active blocks, scheduled first, overlaps the hot
// waves). z >= 1: clean hot path for image b = z-1 (the empirically optimal
// 59.0us body — every measured perturbation of it was equal or worse).
__global__ __launch_bounds__(256)
void loss_kernel(const float* __restrict__ inp,
                 const float* __restrict__ tgt,
                 float* __restrict__ out) {
    const int tid = threadIdx.y * 32 + threadIdx.x;
    if (blockIdx.z == 0) {         // border slice (block-uniform branch)
        if (blockIdx.y * gridDim.x + blockIdx.x >= NBBLK) return;
        border_path(inp, tgt, out, tid);
        return;
    }
    const int b = blockIdx.z - 1;

    const int x = blockIdx.x * 32 + threadIdx.x;
    const int y = blockIdx.y * 8 + threadIdx.y;
    const int pidx = y * WW + x;

    const float* pi = inp + b * CHW + pidx;
    const float* pt = tgt + b * CHW + pidx;

    const float i0 = pi[0], i1 = pi[HWSZ], i2 = pi[2 * HWSZ];
    const float t0 = pt[0], t1 = pt[HWSZ], t2 = pt[2 * HWSZ];

    float wky[4];
    wky[0] = 1.0f;
    wky[1] = __expf(-1.0f * INV2SS);
    wky[2] = __expf(-4.0f * INV2SS);
    wky[3] = __expf(-9.0f * INV2SS);

    float pacc = 0.0f;

#pragma unroll
    for (int dy = 0; dy <= 3; dy++) {
        const bool vy = (y + dy) < HH;
#pragma unroll
        for (int dx = -3; dx <= 3; dx++) {
            if (dy == 0 && dx <= 0) continue;      // compile-time
            const bool v = vy && ((unsigned)(x + dx) < (unsigned)WW);
            if (v) {
                const int q = dy * WW + dx;        // compile-time immediate
                const float iq0 = __ldg(pi + q);
                const float iq1 = __ldg(pi + q + HWSZ);
                const float iq2 = __ldg(pi + q + 2 * HWSZ);
                const float tq0 = __ldg(pt + q);
                const float tq1 = __ldg(pt + q + HWSZ);
                const float tq2 = __ldg(pt + q + 2 * HWSZ);

                const float d0 = i0 - iq0, d1 = i1 - iq1, d2 = i2 - iq2;
                const float e0 = t0 - tq0, e1 = t1 - tq1, e2 = t2 - tq2;

                const float cd = fmaf(e0, e0, fmaf(e1, e1, e2 * e2));
                const int adx = dx < 0 ? -dx : dx;
                const float ws = wky[dy] * wky[adx];
                const float sconst = (float)(dy * dy + dx * dx) * INV2SS;
                const float wcs = __expf(-fmaf(cd, INV2SC, sconst)); // ws*wc

                const float sm = lp_term(d0) + lp_term(d1) + lp_term(d2);
                const float ed = lp_term(fabsf(d0) - fabsf(e0))
                               + lp_term(fabsf(d1) - fabsf(e1))
                               + lp_term(fabsf(d2) - fabsf(e2));

                pacc = fmaf(wcs, sm, pacc);
                pacc = fmaf(ws - wcs, ed, pacc);
            }
        }
    }

    const float l2 = (i0 - t0) * (i0 - t0)
                   + (i1 - t1) * (i1 - t1)
                   + (i2 - t2) * (i2 - t2);
    const float acc = fmaf(2.0f, pacc, l2);

    reduce_add(acc, out, tid);
}

extern "C" void kernel_launch(void* const* d_in, const int* in_sizes, int n_in,
                              void* d_out, int out_size) {
    (void)in_sizes; (void)n_in;
    const float* inp = (const float*)d_in[0];
    const float* tgt = (const float*)d_in[1];
    float* out = (float*)d_out;

    if (out_size >= 1) cudaMemsetAsync(out, 0, sizeof(float));

    dim3 block(32, 8, 1);
    dim3 grid(WW / 32, HH / 8, BB + 1);   // z==0: border; z-1 = image index
    loss_kernel<<<grid, block>>>(inp, tgt, out);
}